// round 1
// baseline (speedup 1.0000x reference)
#include <cuda_runtime.h>
#include <cstdint>

#define BATCH   16384
#define NF      768
#define FT      1024
#define NROWS   (2*BATCH)      // virtual rows: [0,16384)=stm, [16384,32768)=nstm
#define MAXI    128            // max stored nonzeros per row (mean 32, 17 sigma headroom)
#define NSLICE  16
#define OSLICE  64             // FT / NSLICE
#define PAD     65             // smem row pad -> conflict-free LDS
#define RB      37             // row-groups per slice: 16*37 = 592 blocks = 4 full waves
#define SMEM_BYTES (NF * PAD * 4)   // 199,680 B

// ---- scratch (device globals; no allocation) ----
__device__ uint16_t g_idx[(size_t)NROWS * MAXI];   // 8 MB: compacted active-feature indices
__device__ int      g_cnt[NROWS];
__device__ float    g_acc[64 * BATCH];             // 4 MB: per-(slice,persp,warp-half) partial dots

// ============================================================================
// Kernel 1: warp-per-row nonzero scan + compaction (ballot/popc).
// Reads each board exactly once (coalesced float4), writes ~32 u16 indices/row.
// ============================================================================
__global__ __launch_bounds__(256) void scan_kernel(const float* __restrict__ stm,
                                                   const float* __restrict__ nstm) {
    int gtid = blockIdx.x * 256 + threadIdx.x;
    int warp = gtid >> 5;
    int lane = gtid & 31;
    if (warp >= NROWS) return;

    const float* row = (warp < BATCH) ? (stm + (size_t)warp * NF)
                                      : (nstm + (size_t)(warp - BATCH) * NF);
    const float4* row4 = (const float4*)row;
    uint16_t* out = g_idx + (size_t)warp * MAXI;

    int base = 0;
    #pragma unroll
    for (int j = 0; j < 6; j++) {                    // 6 * 32 lanes * 4 floats = 768
        float4 v = row4[lane + 32 * j];
        float vv[4] = {v.x, v.y, v.z, v.w};
        #pragma unroll
        for (int c = 0; c < 4; c++) {
            bool p = (vv[c] != 0.0f);                // board entries are exactly {0,1}
            unsigned m = __ballot_sync(0xffffffffu, p);
            if (p) {
                int pos = base + __popc(m & ((1u << lane) - 1u));
                if (pos < MAXI)
                    out[pos] = (uint16_t)(4 * (lane + 32 * j) + c);
            }
            base += __popc(m);
        }
    }
    if (lane == 0) g_cnt[warp] = (base < MAXI) ? base : MAXI;
}

// ============================================================================
// Kernel 2: sparse accumulate from smem-resident W slice + fused epilogue.
// Block = (slice s, row-group rg). smem: W_ftT slice [768][64] fp32, pad 65.
// Threads: 256 = 64 outputs x 4 concurrent rows; each warp serves one row
// (uniform count, uniform index stream, conflict-free LDS across its 32 outs).
// Epilogue: screlu -> * W_out -> warp reduce -> deterministic slot write.
// ============================================================================
__global__ __launch_bounds__(256, 1) void accum_kernel(const float* __restrict__ W_ft,
                                                       const float* __restrict__ b_ft,
                                                       const float* __restrict__ W_out) {
    extern __shared__ float W_sm[];   // [NF][PAD], element f*PAD + o

    const int s  = blockIdx.x / RB;
    const int rg = blockIdx.x % RB;

    // ---- load W slice (outputs [s*64, s*64+64)), transpose into smem ----
    const float4* Wg = (const float4*)W_ft;
    for (int l = threadIdx.x; l < (OSLICE * NF) / 4; l += 256) {
        int g = l * 4;
        int o = g / NF;
        int f = g % NF;                  // multiple of 4, same W row for all 4 elems
        float4 v = Wg[((size_t)(s * OSLICE + o) * NF + f) >> 2];
        W_sm[(f + 0) * PAD + o] = v.x;
        W_sm[(f + 1) * PAD + o] = v.y;
        W_sm[(f + 2) * PAD + o] = v.z;
        W_sm[(f + 3) * PAD + o] = v.w;
    }
    __syncthreads();

    const int o    = threadIdx.x & 63;       // output within slice
    const int rl   = threadIdx.x >> 6;       // row lane 0..3
    const int half = o >> 5;                 // warp half within the 64 outputs
    const int og   = s * OSLICE + o;

    const float bft = b_ft[og];
    const float w_stm  = W_out[og];          // W_out row-major [1, 2048]
    const float w_nstm = W_out[FT + og];

    for (int R0 = rg * 4; R0 < NROWS; R0 += RB * 4) {
        const int R = R0 + rl;               // R0 multiple of 4 and < 32768 -> R valid
        const int cnt = g_cnt[R];
        const uint16_t* ip = g_idx + (size_t)R * MAXI;

        float a0 = 0.f, a1 = 0.f;
        int k = 0;
        for (; k + 8 <= cnt; k += 8) {
            uint4 u = *(const uint4*)(ip + k);       // 16B-aligned, warp-uniform
            int i0 = u.x & 0xffff, i1 = u.x >> 16;
            int i2 = u.y & 0xffff, i3 = u.y >> 16;
            int i4 = u.z & 0xffff, i5 = u.z >> 16;
            int i6 = u.w & 0xffff, i7 = u.w >> 16;
            a0 += W_sm[i0 * PAD + o];  a1 += W_sm[i1 * PAD + o];
            a0 += W_sm[i2 * PAD + o];  a1 += W_sm[i3 * PAD + o];
            a0 += W_sm[i4 * PAD + o];  a1 += W_sm[i5 * PAD + o];
            a0 += W_sm[i6 * PAD + o];  a1 += W_sm[i7 * PAD + o];
        }
        for (; k < cnt; k++)
            a0 += W_sm[(int)ip[k] * PAD + o];

        float pre = bft + a0 + a1;
        pre = fminf(fmaxf(pre, 0.0f), 1.0f);
        float contrib = pre * pre * ((R < BATCH) ? w_stm : w_nstm);

        #pragma unroll
        for (int off = 16; off; off >>= 1)
            contrib += __shfl_xor_sync(0xffffffffu, contrib, off);

        if ((threadIdx.x & 31) == 0) {
            const int b = R & (BATCH - 1);
            const int p = R >> 14;
            const int slot = s * 4 + p * 2 + half;   // unique (s,p,half) per b
            g_acc[(size_t)slot * BATCH + b] = contrib;
        }
    }
}

// ============================================================================
// Kernel 3: sum 64 deterministic partials, add b_out, sigmoid.
// ============================================================================
__global__ __launch_bounds__(256) void finalize_kernel(const float* __restrict__ b_out,
                                                       float* __restrict__ out) {
    int b = blockIdx.x * 256 + threadIdx.x;
    if (b >= BATCH) return;
    float x = b_out[0];
    #pragma unroll
    for (int sl = 0; sl < 64; sl++)
        x += g_acc[(size_t)sl * BATCH + b];
    out[b] = 1.0f / (1.0f + expf(-x));
}

extern "C" void kernel_launch(void* const* d_in, const int* in_sizes, int n_in,
                              void* d_out, int out_size) {
    const float* stm   = (const float*)d_in[0];
    const float* nstm  = (const float*)d_in[1];
    const float* W_ft  = (const float*)d_in[2];
    const float* b_ft  = (const float*)d_in[3];
    const float* W_out = (const float*)d_in[4];
    const float* b_out = (const float*)d_in[5];
    float* out = (float*)d_out;

    cudaFuncSetAttribute(accum_kernel,
                         cudaFuncAttributeMaxDynamicSharedMemorySize, SMEM_BYTES);

    scan_kernel<<<NROWS / 8, 256>>>(stm, nstm);              // 4096 blocks, warp/row
    accum_kernel<<<NSLICE * RB, 256, SMEM_BYTES>>>(W_ft, b_ft, W_out);  // 592 blocks
    finalize_kernel<<<(BATCH + 255) / 256, 256>>>(b_out, out);
}

// round 2
// speedup vs baseline: 4.0646x; 4.0646x over previous
#include <cuda_runtime.h>
#include <cstdint>

#define BATCH   16384
#define NF      768
#define FT      1024
#define NROWS   (2*BATCH)      // virtual rows: [0,16384)=stm, [16384,32768)=nstm
#define MAXI    128            // max stored nonzeros per row (mean 32)
#define NSLICE  16
#define OSLICE  64             // FT / NSLICE
#define PAD     66             // even pad -> 8B-aligned conflict-free float2 LDS
#define RB      18             // blocks per slice: 16*18 = 288 blocks (~2 waves)
#define THREADS 1024           // 32 warps: 1 warp per row, 32 rows in flight
#define NSLOT   32             // 16 slices x 2 perspectives
#define SMEM_BYTES ((NF + 1) * PAD * 4)   // 203,016 B (row NF is the zero dummy row)

// ---- scratch (device globals; no allocation) ----
__device__ uint16_t g_idx[(size_t)NROWS * MAXI];   // 8 MB compacted indices (padded to x8)
__device__ int      g_cnt[NROWS];
__device__ float    g_acc[NSLOT * BATCH];          // 2 MB deterministic partials

// ============================================================================
// Kernel 1: warp-per-row nonzero scan + compaction (ballot/popc).
// Pads each row's index list to a multiple of 8 with dummy index NF (=768),
// which maps to a zeroed smem row in the accum kernel -> no masking needed.
// ============================================================================
__global__ __launch_bounds__(256) void scan_kernel(const float* __restrict__ stm,
                                                   const float* __restrict__ nstm) {
    int gtid = blockIdx.x * 256 + threadIdx.x;
    int warp = gtid >> 5;
    int lane = gtid & 31;
    if (warp >= NROWS) return;

    const float* row = (warp < BATCH) ? (stm + (size_t)warp * NF)
                                      : (nstm + (size_t)(warp - BATCH) * NF);
    const float4* row4 = (const float4*)row;
    uint16_t* out = g_idx + (size_t)warp * MAXI;

    int base = 0;
    #pragma unroll
    for (int j = 0; j < 6; j++) {                    // 6 * 32 lanes * 4 floats = 768
        float4 v = row4[lane + 32 * j];
        float vv[4] = {v.x, v.y, v.z, v.w};
        #pragma unroll
        for (int c = 0; c < 4; c++) {
            bool p = (vv[c] != 0.0f);                // board entries are exactly {0,1}
            unsigned m = __ballot_sync(0xffffffffu, p);
            if (p) {
                int pos = base + __popc(m & ((1u << lane) - 1u));
                if (pos < MAXI)
                    out[pos] = (uint16_t)(4 * (lane + 32 * j) + c);
            }
            base += __popc(m);
        }
    }
    int cnt = (base < MAXI) ? base : MAXI;
    int padded = (cnt + 7) & ~7;
    if (padded > MAXI) padded = MAXI;
    if (lane < padded - cnt) out[cnt + lane] = (uint16_t)NF;   // dummy -> zero row
    if (lane == 0) g_cnt[warp] = cnt;
}

// ============================================================================
// Kernel 2: sparse accumulate from smem-resident W slice + fused epilogue.
// Block = (slice s, row-group rg). smem: W_ftT slice [769][66] fp32
// (row 768 zeroed for dummy indices). 1024 threads = 32 warps; warp w serves
// row R, lane l serves outputs {2l, 2l+1} via float2 LDS (conflict-free).
// Index words are prefetched unconditionally (6x uint4 = 48 idx, covers
// ~99.8% of rows; global tail loop for the rest) -> one exposed L2 latency.
// ============================================================================
__global__ __launch_bounds__(THREADS, 1) void accum_kernel(const float* __restrict__ W_ft,
                                                           const float* __restrict__ b_ft,
                                                           const float* __restrict__ W_out) {
    extern __shared__ float W_sm[];   // [NF+1][PAD]

    const int s  = blockIdx.x / RB;
    const int rg = blockIdx.x % RB;

    // ---- load W slice (outputs [s*64, s*64+64)), transpose into smem ----
    const float4* Wg = (const float4*)W_ft;
    for (int l = threadIdx.x; l < (OSLICE * NF) / 4; l += THREADS) {
        int g = l * 4;
        int o = g / NF;
        int f = g % NF;                  // multiple of 4, same W row for all 4 elems
        float4 v = Wg[((size_t)(s * OSLICE + o) * NF + f) >> 2];
        W_sm[(f + 0) * PAD + o] = v.x;
        W_sm[(f + 1) * PAD + o] = v.y;
        W_sm[(f + 2) * PAD + o] = v.z;
        W_sm[(f + 3) * PAD + o] = v.w;
    }
    if (threadIdx.x < PAD) W_sm[NF * PAD + threadIdx.x] = 0.0f;   // dummy row
    __syncthreads();

    const int w    = threadIdx.x >> 5;       // warp = row lane 0..31
    const int lane = threadIdx.x & 31;
    const int oo   = lane << 1;              // output pair within slice
    const int og   = s * OSLICE + oo;

    const float2 bf = *(const float2*)(b_ft + og);
    const float2 wo_stm  = *(const float2*)(W_out + og);
    const float2 wo_nstm = *(const float2*)(W_out + FT + og);

    const float* Wl = W_sm + oo;             // thread-local base

    for (int R = rg * 32 + w; R < NROWS; R += RB * 32) {
        const int cnt = g_cnt[R];
        const uint16_t* ip = g_idx + (size_t)R * MAXI;

        // unconditional parallel prefetch of 48 indices (valid scratch memory)
        uint4 u0 = ((const uint4*)ip)[0];
        uint4 u1 = ((const uint4*)ip)[1];
        uint4 u2 = ((const uint4*)ip)[2];
        uint4 u3 = ((const uint4*)ip)[3];
        uint4 u4 = ((const uint4*)ip)[4];
        uint4 u5 = ((const uint4*)ip)[5];

        float a0 = 0.f, a1 = 0.f, a2 = 0.f, a3 = 0.f;
        const int ng = (cnt + 7) >> 3;       // index list padded to x8 with dummies

        #define GRP(U)  {                                                        \
            float2 v;                                                            \
            v = *(const float2*)(Wl + (int)(U.x & 0xffffu) * PAD); a0 += v.x; a1 += v.y; \
            v = *(const float2*)(Wl + (int)(U.x >> 16)     * PAD); a2 += v.x; a3 += v.y; \
            v = *(const float2*)(Wl + (int)(U.y & 0xffffu) * PAD); a0 += v.x; a1 += v.y; \
            v = *(const float2*)(Wl + (int)(U.y >> 16)     * PAD); a2 += v.x; a3 += v.y; \
            v = *(const float2*)(Wl + (int)(U.z & 0xffffu) * PAD); a0 += v.x; a1 += v.y; \
            v = *(const float2*)(Wl + (int)(U.z >> 16)     * PAD); a2 += v.x; a3 += v.y; \
            v = *(const float2*)(Wl + (int)(U.w & 0xffffu) * PAD); a0 += v.x; a1 += v.y; \
            v = *(const float2*)(Wl + (int)(U.w >> 16)     * PAD); a2 += v.x; a3 += v.y; }

        if (ng > 0) GRP(u0)
        if (ng > 1) GRP(u1)
        if (ng > 2) GRP(u2)
        if (ng > 3) GRP(u3)
        if (ng > 4) GRP(u4)
        if (ng > 5) GRP(u5)
        for (int k = 48; k < cnt; k++) {          // rare tail (cnt > 48)
            float2 v = *(const float2*)(Wl + (int)ip[k] * PAD);
            a0 += v.x; a1 += v.y;
        }
        #undef GRP

        float p0 = fminf(fmaxf(bf.x + a0 + a2, 0.0f), 1.0f);
        float p1 = fminf(fmaxf(bf.y + a1 + a3, 0.0f), 1.0f);
        const float2 wo = (R < BATCH) ? wo_stm : wo_nstm;
        float contrib = p0 * p0 * wo.x + p1 * p1 * wo.y;

        #pragma unroll
        for (int off = 16; off; off >>= 1)
            contrib += __shfl_xor_sync(0xffffffffu, contrib, off);

        if (lane == 0) {
            const int b = R & (BATCH - 1);
            const int p = R >> 14;
            g_acc[(size_t)(s * 2 + p) * BATCH + b] = contrib;
        }
    }
}

// ============================================================================
// Kernel 3: sum 32 deterministic partials, add b_out, sigmoid.
// ============================================================================
__global__ __launch_bounds__(256) void finalize_kernel(const float* __restrict__ b_out,
                                                       float* __restrict__ out) {
    int b = blockIdx.x * 256 + threadIdx.x;
    if (b >= BATCH) return;
    float x = b_out[0];
    #pragma unroll
    for (int sl = 0; sl < NSLOT; sl++)
        x += g_acc[(size_t)sl * BATCH + b];
    out[b] = 1.0f / (1.0f + expf(-x));
}

extern "C" void kernel_launch(void* const* d_in, const int* in_sizes, int n_in,
                              void* d_out, int out_size) {
    const float* stm   = (const float*)d_in[0];
    const float* nstm  = (const float*)d_in[1];
    const float* W_ft  = (const float*)d_in[2];
    const float* b_ft  = (const float*)d_in[3];
    const float* W_out = (const float*)d_in[4];
    const float* b_out = (const float*)d_in[5];
    float* out = (float*)d_out;

    cudaFuncSetAttribute(accum_kernel,
                         cudaFuncAttributeMaxDynamicSharedMemorySize, SMEM_BYTES);

    scan_kernel<<<NROWS / 8, 256>>>(stm, nstm);                          // 4096 blocks
    accum_kernel<<<NSLICE * RB, THREADS, SMEM_BYTES>>>(W_ft, b_ft, W_out); // 288 blocks
    finalize_kernel<<<(BATCH + 255) / 256, 256>>>(b_out, out);
}

// round 3
// speedup vs baseline: 6.7743x; 1.6667x over previous
#include <cuda_runtime.h>
#include <cuda_fp16.h>
#include <cstdint>

#define BATCH   16384
#define NF      768
#define FT      1024
#define NROWS   (2*BATCH)      // virtual rows: [0,16384)=stm, [16384,32768)=nstm
#define MAXI    128            // max stored nonzeros per row (mean 32)
#define NSL     8              // output slices
#define OSL     128            // outputs per slice
#define RB      18             // blocks per slice: 8*18 = 144 blocks = 1 wave
#define THREADS 1024           // 32 warps: 1 warp per row
#define NSLOT   16             // 8 slices x 2 perspectives
#define SMEM_BYTES ((NF + 1) * OSL * 2)   // 196,864 B (__half, row NF = zero dummy)

// ---- scratch (device globals; no allocation) ----
__device__ uint16_t g_idx[(size_t)NROWS * MAXI];   // 8 MB compacted indices (padded to x8)
__device__ int      g_cnt[NROWS];
__device__ float    g_acc[NSLOT * BATCH];          // 1 MB deterministic partials

// ============================================================================
// Kernel 1: warp-per-row nonzero scan + compaction (ballot/popc).
// Pads each row's index list to a multiple of 8 with dummy index NF (=768),
// which maps to a zeroed smem row in the accum kernel -> no masking needed.
// ============================================================================
__global__ __launch_bounds__(256) void scan_kernel(const float* __restrict__ stm,
                                                   const float* __restrict__ nstm) {
    int gtid = blockIdx.x * 256 + threadIdx.x;
    int warp = gtid >> 5;
    int lane = gtid & 31;
    if (warp >= NROWS) return;

    const float* row = (warp < BATCH) ? (stm + (size_t)warp * NF)
                                      : (nstm + (size_t)(warp - BATCH) * NF);
    const float4* row4 = (const float4*)row;
    uint16_t* out = g_idx + (size_t)warp * MAXI;

    int base = 0;
    #pragma unroll
    for (int j = 0; j < 6; j++) {                    // 6 * 32 lanes * 4 floats = 768
        float4 v = row4[lane + 32 * j];
        float vv[4] = {v.x, v.y, v.z, v.w};
        #pragma unroll
        for (int c = 0; c < 4; c++) {
            bool p = (vv[c] != 0.0f);                // board entries are exactly {0,1}
            unsigned m = __ballot_sync(0xffffffffu, p);
            if (p) {
                int pos = base + __popc(m & ((1u << lane) - 1u));
                if (pos < MAXI)
                    out[pos] = (uint16_t)(4 * (lane + 32 * j) + c);
            }
            base += __popc(m);
        }
    }
    int cnt = (base < MAXI) ? base : MAXI;
    int padded = (cnt + 7) & ~7;
    if (padded > MAXI) padded = MAXI;
    if (lane < padded - cnt) out[cnt + lane] = (uint16_t)NF;   // dummy -> zero row
    if (lane == 0) g_cnt[warp] = cnt;
}

// ============================================================================
// Kernel 2: sparse accumulate from fp16 smem-resident W slice + fused epilogue.
// Block = (slice s, rg). smem: W_ftT slice [769][128] __half (row 768 zeroed).
// 32 warps: warp w serves row R; lane l serves outputs {4l..4l+3} via one
// LDS.64 (2x half2) per active feature -> 256B/warp-gather, conflict-free.
// Accumulate in 4 alternating half2 accumulators (HADD2), fp32 epilogue:
// screlu -> * W_out -> warp reduce -> deterministic slot write.
// ============================================================================
__global__ __launch_bounds__(THREADS, 1) void accum_kernel(const float* __restrict__ W_ft,
                                                           const float* __restrict__ b_ft,
                                                           const float* __restrict__ W_out) {
    extern __shared__ __half W_sm[];   // [(NF+1)][OSL]

    const int s  = blockIdx.x / RB;
    const int rg = blockIdx.x % RB;
    const int obase = s * OSL;

    // ---- load W slice, convert to fp16, transpose into smem ----
    // pair-task p: output pair op=2*(p%64), feature quad f=4*(p/64).
    // Stores: half2(w[op][f+i], w[op+1][f+i]) at halves (f+i)*OSL + op
    //   -> word index (f+i)*64 + op/2: consecutive op/2 across warp = 32 banks.
    for (int p = threadIdx.x; p < 64 * (NF / 4); p += THREADS) {
        int fq = p >> 6;                 // 0..191
        int op = (p & 63) << 1;          // even output 0..126
        float4 a = *(const float4*)(W_ft + (size_t)(obase + op)     * NF + 4 * fq);
        float4 b = *(const float4*)(W_ft + (size_t)(obase + op + 1) * NF + 4 * fq);
        __half2* dst = (__half2*)W_sm;
        int w0 = (4 * fq) * (OSL / 2) + (op >> 1);
        dst[w0            ] = __floats2half2_rn(a.x, b.x);
        dst[w0 + OSL / 2  ] = __floats2half2_rn(a.y, b.y);
        dst[w0 + OSL      ] = __floats2half2_rn(a.z, b.z);
        dst[w0 + 3*OSL / 2] = __floats2half2_rn(a.w, b.w);
    }
    if (threadIdx.x < OSL / 2)           // zero dummy row NF
        ((__half2*)W_sm)[NF * (OSL / 2) + threadIdx.x] = __floats2half2_rn(0.f, 0.f);
    __syncthreads();

    const int w    = threadIdx.x >> 5;
    const int lane = threadIdx.x & 31;
    const int og   = obase + lane * 4;   // this lane's 4 outputs

    const float4 bf      = *(const float4*)(b_ft + og);
    const float4 wo_stm  = *(const float4*)(W_out + og);
    const float4 wo_nstm = *(const float4*)(W_out + FT + og);

    const char* Wl = (const char*)W_sm + lane * 8;   // lane base (bytes)

    for (int R = rg * 32 + w; R < NROWS; R += RB * 32) {
        const int cnt = g_cnt[R];
        const uint16_t* ip = g_idx + (size_t)R * MAXI;

        // unconditional parallel prefetch of 48 indices
        uint4 u0 = ((const uint4*)ip)[0];
        uint4 u1 = ((const uint4*)ip)[1];
        uint4 u2 = ((const uint4*)ip)[2];
        uint4 u3 = ((const uint4*)ip)[3];
        uint4 u4 = ((const uint4*)ip)[4];
        uint4 u5 = ((const uint4*)ip)[5];

        __half2 z = __floats2half2_rn(0.f, 0.f);
        __half2 aa0 = z, aa1 = z, ba0 = z, ba1 = z;  // 2 alternating acc pairs
        const int ng = (cnt + 7) >> 3;               // padded to x8 with dummies

        #define G1(IDX, A0, A1) { \
            uint2 v = *(const uint2*)(Wl + (int)(IDX) * (OSL * 2)); \
            A0 = __hadd2(A0, *(__half2*)&v.x); A1 = __hadd2(A1, *(__half2*)&v.y); }
        #define GRP(U) { \
            G1(U.x & 0xffffu, aa0, aa1)  G1(U.x >> 16, ba0, ba1) \
            G1(U.y & 0xffffu, aa0, aa1)  G1(U.y >> 16, ba0, ba1) \
            G1(U.z & 0xffffu, aa0, aa1)  G1(U.z >> 16, ba0, ba1) \
            G1(U.w & 0xffffu, aa0, aa1)  G1(U.w >> 16, ba0, ba1) }

        if (ng > 0) GRP(u0)
        if (ng > 1) GRP(u1)
        if (ng > 2) GRP(u2)
        if (ng > 3) GRP(u3)
        if (ng > 4) GRP(u4)
        if (ng > 5) GRP(u5)
        for (int k = 48; k < cnt; k++)               // rare tail (cnt > 48)
            G1(ip[k], aa0, aa1)
        #undef GRP
        #undef G1

        float2 xa = __half22float2(aa0), xb = __half22float2(ba0);
        float2 ya = __half22float2(aa1), yb = __half22float2(ba1);
        float p0 = fminf(fmaxf(bf.x + xa.x + xb.x, 0.f), 1.f);
        float p1 = fminf(fmaxf(bf.y + xa.y + xb.y, 0.f), 1.f);
        float p2 = fminf(fmaxf(bf.z + ya.x + yb.x, 0.f), 1.f);
        float p3 = fminf(fmaxf(bf.w + ya.y + yb.y, 0.f), 1.f);
        const float4 wo = (R < BATCH) ? wo_stm : wo_nstm;
        float contrib = p0*p0*wo.x + p1*p1*wo.y + p2*p2*wo.z + p3*p3*wo.w;

        #pragma unroll
        for (int off = 16; off; off >>= 1)
            contrib += __shfl_xor_sync(0xffffffffu, contrib, off);

        if (lane == 0) {
            const int b = R & (BATCH - 1);
            const int p = R >> 14;
            g_acc[(size_t)(s * 2 + p) * BATCH + b] = contrib;
        }
    }
}

// ============================================================================
// Kernel 3: sum 16 deterministic partials, add b_out, sigmoid.
// ============================================================================
__global__ __launch_bounds__(256) void finalize_kernel(const float* __restrict__ b_out,
                                                       float* __restrict__ out) {
    int b = blockIdx.x * 256 + threadIdx.x;
    if (b >= BATCH) return;
    float x = b_out[0];
    #pragma unroll
    for (int sl = 0; sl < NSLOT; sl++)
        x += g_acc[(size_t)sl * BATCH + b];
    out[b] = 1.0f / (1.0f + expf(-x));
}

extern "C" void kernel_launch(void* const* d_in, const int* in_sizes, int n_in,
                              void* d_out, int out_size) {
    const float* stm   = (const float*)d_in[0];
    const float* nstm  = (const float*)d_in[1];
    const float* W_ft  = (const float*)d_in[2];
    const float* b_ft  = (const float*)d_in[3];
    const float* W_out = (const float*)d_in[4];
    const float* b_out = (const float*)d_in[5];
    float* out = (float*)d_out;

    cudaFuncSetAttribute(accum_kernel,
                         cudaFuncAttributeMaxDynamicSharedMemorySize, SMEM_BYTES);

    scan_kernel<<<NROWS / 8, 256>>>(stm, nstm);                            // 4096 blocks
    accum_kernel<<<NSL * RB, THREADS, SMEM_BYTES>>>(W_ft, b_ft, W_out);    // 144 blocks
    finalize_kernel<<<(BATCH + 255) / 256, 256>>>(b_out, out);
}